// round 9
// baseline (speedup 1.0000x reference)
#include <cuda_runtime.h>

#define BATCH   1024
#define TSTEPS  100
#define L0      30
#define C1      16
#define L1      24
#define K1      7
#define C2      32
#define L2      20
#define K2      5
#define C3      64
#define L3      18
#define K3      3
#define F1      1152   // 64*18
#define H1      256
#define NC      10

#define NTHREADS 256
#define S1ROW 52     // padded word stride per ci-pair, s1 (24 l * 2 + pad)
#define S2ROW 44     // padded word stride per ci-pair, s2 (20 l * 2 + pad)

typedef unsigned long long u64;
typedef unsigned short u16;

// Transposed fc1 weights: fw1T[i*H1 + j] = fw1[j*F1 + i]
__device__ __align__(16) float g_fw1T[F1 * H1];

__global__ void transpose_fw1_kernel(const float* __restrict__ fw1) {
    int idx = blockIdx.x * blockDim.x + threadIdx.x;
    if (idx < H1 * F1) {
        int j = idx / F1;
        int i = idx - j * F1;
        g_fw1T[i * H1 + j] = fw1[idx];
    }
}

// ---- f32x2 helpers ----
__device__ __forceinline__ u64 ffma2(u64 a, u64 b, u64 c) {
    u64 d; asm("fma.rn.f32x2 %0, %1, %2, %3;" : "=l"(d) : "l"(a), "l"(b), "l"(c)); return d;
}
__device__ __forceinline__ u64 fadd2(u64 a, u64 b) {
    u64 d; asm("add.rn.f32x2 %0, %1, %2;" : "=l"(d) : "l"(a), "l"(b)); return d;
}
__device__ __forceinline__ u64 pack2(float lo, float hi) {
    u64 r; asm("mov.b64 %0, {%1, %2};" : "=l"(r) : "f"(lo), "f"(hi)); return r;
}
__device__ __forceinline__ void unpack2(u64 v, float& lo, float& hi) {
    asm("mov.b64 {%0, %1}, %2;" : "=f"(lo), "=f"(hi) : "l"(v));
}
__device__ __forceinline__ u64 lds64(const float* p) { return *(const u64*)p; }

// half-scoped barrier: 128 threads, ids 1 (half 0) / 2 (half 1)
__device__ __forceinline__ void barh(int id) {
    asm volatile("bar.sync %0, 128;" :: "r"(id) : "memory");
}

// LIF: reset from PREVIOUS mem (subtract), spike on new mem.
// No FMA contraction: match reference op sequence 0.9*m + h - reset.
__device__ __forceinline__ float lif_new_mem(float m_old, float h) {
    float reset = (m_old > 1.0f) ? 1.0f : 0.0f;
    return __fadd_rn(__fadd_rn(__fmul_rn(0.9f, m_old), h), -reset);
}

// Dense conv block on f32x2 pairs, paired-row spike loads (broadcast LDS.128).
// Spikes: [p][l][2] with stride SROW words per p; sbase pre-offset by l0*2.
// Order per output q: bias, then p asc, d asc, k asc — identical to prior rounds.
template<int LEN, int K, int NP, int COUT, int SROW>
__device__ __forceinline__ void conv_x2(const float* __restrict__ swp,
                                        const float* __restrict__ sbase,
                                        int co, u64 binit, u64* acc) {
    constexpr int WIN = LEN + K - 1;     // even by construction
    constexpr int WP = WIN / 2;
    #pragma unroll
    for (int q = 0; q < LEN; q++) acc[q] = binit;
    #pragma unroll 4
    for (int p = 0; p < NP; p++) {
        u64 w[K];
        #pragma unroll
        for (int k = 0; k < K; k++)
            w[k] = lds64(swp + ((p * K + k) * COUT + co) * 2);
        const ulonglong2* sp = (const ulonglong2*)(sbase + p * SROW);
        #pragma unroll
        for (int dp = 0; dp < WP; dp++) {
            ulonglong2 v = sp[dp];
            #pragma unroll
            for (int k = 0; k < K; k++) {
                int q0 = 2 * dp - k;
                if (q0 >= 0 && q0 < LEN) acc[q0] = ffma2(w[k], v.x, acc[q0]);
            }
            #pragma unroll
            for (int k = 0; k < K; k++) {
                int q1 = 2 * dp + 1 - k;
                if (q1 >= 0 && q1 < LEN) acc[q1] = ffma2(w[k], v.y, acc[q1]);
            }
        }
    }
}

// smem layout (words)
#define OFF_SW1T 0        // 112: [k*16+co]
#define OFF_SB1  112      // 16
#define OFF_SW2P 128      // 2560: [((p*5+k)*32+co)*2+e]
#define OFF_SW3P 2688     // 6144: [((p*3+k)*64+co)*2+e]
#define OFF_XB   8832     // 2*2*32 = 128: [half][buf][l]
#define OFF_S1   8960     // 2*416: [half][p*52 + l*2 + e]
#define OFF_S2   9792     // 2*704: [half][p*44 + l*2 + e]
#define OFF_S4   11200    // 2*256: [half][j]
#define OFF_MSK  11712    // 2*128: [half][T*64+co]
#define OFF_NACT 11968    // 2*4
#define OFF_ACT  11976    // 2*576 words = 2*1152 u16 (byte 47904, 8-aligned)
#define SMEM_WORDS 13128
#define SMEM_BYTES (SMEM_WORDS * 4)

__global__ __launch_bounds__(NTHREADS, 4)
void snn_kernel(const float* __restrict__ x,
                const float* __restrict__ w1, const float* __restrict__ b1,
                const float* __restrict__ w2, const float* __restrict__ b2,
                const float* __restrict__ w3, const float* __restrict__ b3,
                const float* __restrict__ fb1,
                const float* __restrict__ fw2, const float* __restrict__ fb2,
                float* __restrict__ out)
{
    extern __shared__ float smem[];
    float* sw1t = smem + OFF_SW1T;
    float* sb1  = smem + OFF_SB1;
    float* sw2p = smem + OFF_SW2P;
    float* sw3p = smem + OFF_SW3P;

    const int tid  = threadIdx.x;
    const int lane = tid & 31;
    const int warp = tid >> 5;
    const int half = warp >> 2;            // 0: warps 0-3 (sample A), 1: warps 4-7 (sample B)
    const int hwarp = warp & 3;
    const int htid = (hwarp << 5) | lane;  // 0..127 within half
    const int b = 2 * blockIdx.x + half;
    const int barid = 1 + half;

    float* xb   = smem + OFF_XB + half * 64;
    float* s1p  = smem + OFF_S1 + half * 416;   // [p*52 + l*2 + e]
    float* s2p  = smem + OFF_S2 + half * 704;   // [p*44 + l*2 + e]
    float* s4buf = smem + OFF_S4 + half * 256;
    unsigned* mkbuf = (unsigned*)(smem + OFF_MSK) + half * 128;
    int* nacts = (int*)(smem + OFF_NACT) + half * 4;
    u16* act = (u16*)(smem + OFF_ACT) + half * 1152;   // 4 segments of 288

    // ---- pack weights into smem (all 256 threads) ----
    for (int i = tid; i < C1 * K1; i += NTHREADS) {
        int co = i / K1, k = i - co * K1;
        sw1t[k * C1 + co] = w1[i];
    }
    if (tid < C1) sb1[tid] = b1[tid];
    for (int i = tid; i < C2 * C1 * K2; i += NTHREADS) {
        int co = i / (C1 * K2);
        int r = i - co * (C1 * K2);
        int ci = r / K2, k = r - ci * K2;
        sw2p[(((ci >> 1) * K2 + k) * C2 + co) * 2 + (ci & 1)] = w2[i];
    }
    for (int i = tid; i < C3 * C2 * K3; i += NTHREADS) {
        int co = i / (C2 * K3);
        int r = i - co * (C2 * K3);
        int ci = r / K3, k = r - ci * K3;
        sw3p[(((ci >> 1) * K3 + k) * C3 + co) * 2 + (ci & 1)] = w3[i];
    }
    // x prefetch for t=0
    if (hwarp == 0 && lane < L0)
        xb[lane] = __ldg(&x[b * (L0 * TSTEPS) + lane * TSTEPS]);

    // ---- per-thread register state ----
    float m1r[3] = {0.0f, 0.0f, 0.0f};
    const float b2r = b2[lane];
    float m2r[6] = {0.0f, 0.0f, 0.0f, 0.0f, 0.0f, 0.0f};
    // conv2 groups: lens {6,6,4,4}, starts {0,6,12,16} (even → 16B-aligned windows)
    const int len2 = (hwarp < 2) ? 6 : 4;
    const int l02  = (hwarp < 2) ? hwarp * 6 : 12 + (hwarp - 2) * 4;
    // conv3 groups: lens {10,8}, starts {0,10}
    const int co3 = ((hwarp & 1) << 5) | lane;
    const int T3  = hwarp >> 1;
    const int l03 = T3 * 10;
    const float b3r = b3[co3];
    float m3r[10];
    #pragma unroll
    for (int q = 0; q < 10; q++) m3r[q] = 0.0f;
    float m4a = 0.0f, m4b = 0.0f;
    float m5r[3] = {0.0f, 0.0f, 0.0f};
    __syncthreads();   // full-CTA: weights visible to both halves

    for (int t = 0; t < TSTEPS; t++) {
        // ======== conv1 (1->16, k=7): 128 threads/sample, 3 outputs each ========
        {
            const float* xr = xb + (t & 1) * 32;
            if (hwarp == 0 && lane < L0 && t + 1 < TSTEPS)
                xb[((t + 1) & 1) * 32 + lane] =
                    __ldg(&x[b * (L0 * TSTEPS) + lane * TSTEPS + t + 1]);
            #pragma unroll
            for (int it = 0; it < 3; it++) {
                int idx = htid + it * 128;
                int l = idx >> 4, co = idx & 15;
                float acc = sb1[co];
                #pragma unroll
                for (int k = 0; k < K1; k++)
                    acc = fmaf(sw1t[k * C1 + co], xr[l + k], acc);
                float mn = lif_new_mem(m1r[it], acc);
                m1r[it] = mn;
                s1p[(co >> 1) * S1ROW + l * 2 + (co & 1)] = (mn > 1.0f) ? 1.0f : 0.0f;
            }
        }
        barh(barid);   // S1

        // ======== conv2 (16->32, k=5): co=lane ========
        if (hwarp < 2) {
            u64 acc[6];
            conv_x2<6, K2, 8, C2, S1ROW>(sw2p, s1p + l02 * 2, lane, pack2(b2r, 0.0f), acc);
            #pragma unroll
            for (int q = 0; q < 6; q++) {
                float lo, hi; unpack2(acc[q], lo, hi);
                float h = __fadd_rn(lo, hi);
                float mn = lif_new_mem(m2r[q], h);
                m2r[q] = mn;
                s2p[(lane >> 1) * S2ROW + (l02 + q) * 2 + (lane & 1)] = (mn > 1.0f) ? 1.0f : 0.0f;
            }
        } else {
            u64 acc[4];
            conv_x2<4, K2, 8, C2, S1ROW>(sw2p, s1p + l02 * 2, lane, pack2(b2r, 0.0f), acc);
            #pragma unroll
            for (int q = 0; q < 4; q++) {
                float lo, hi; unpack2(acc[q], lo, hi);
                float h = __fadd_rn(lo, hi);
                float mn = lif_new_mem(m2r[q], h);
                m2r[q] = mn;
                s2p[(lane >> 1) * S2ROW + (l02 + q) * 2 + (lane & 1)] = (mn > 1.0f) ? 1.0f : 0.0f;
            }
        }
        barh(barid);   // S2

        // ======== conv3 (32->64, k=3): co3, lens {10,8} ========
        if (T3 == 0) {
            u64 acc[10];
            conv_x2<10, K3, 16, C3, S2ROW>(sw3p, s2p, co3, pack2(b3r, 0.0f), acc);
            unsigned bits = 0;
            #pragma unroll
            for (int q = 0; q < 10; q++) {
                float lo, hi; unpack2(acc[q], lo, hi);
                float h = __fadd_rn(lo, hi);
                float mn = lif_new_mem(m3r[q], h);
                m3r[q] = mn;
                if (mn > 1.0f) bits |= 1u << q;
            }
            mkbuf[co3] = bits;             // l 0..9
        } else {
            u64 acc[8];
            conv_x2<8, K3, 16, C3, S2ROW>(sw3p, s2p + l03 * 2, co3, pack2(b3r, 0.0f), acc);
            unsigned bits = 0;
            #pragma unroll
            for (int q = 0; q < 8; q++) {
                float lo, hi; unpack2(acc[q], lo, hi);
                float h = __fadd_rn(lo, hi);
                float mn = lif_new_mem(m3r[q], h);
                m3r[q] = mn;
                if (mn > 1.0f) bits |= 1u << q;
            }
            mkbuf[64 + co3] = bits;        // l 10..17 (local bits)
        }
        barh(barid);   // S3

        // ======== build active-index list: all 4 warps, 16 rows each ========
        {
            int r = hwarp * 16 + (lane & 15);
            unsigned m = mkbuf[r] | (mkbuf[64 + r] << 10);   // 18 bits, l ascending
            int cnt = __popc(m);
            int pos = cnt;
            #pragma unroll
            for (int o = 1; o < 16; o <<= 1) {
                int v = __shfl_up_sync(0xffffffff, pos, o);
                if ((lane & 15) >= o) pos += v;
            }
            if (lane == 15) nacts[hwarp] = pos;
            if (lane < 16) {
                u16* ap = act + hwarp * 288 + (pos - cnt);
                int base = r * L3;
                while (m) {
                    int l = __ffs(m) - 1; m &= m - 1;
                    *ap++ = (u16)(base + l);
                }
            }
        }
        barh(barid);   // S3b

        // ======== fc1 (1152->256): 128 threads/sample, 2 outputs each ========
        {
            u64 acc = __ldg((const u64*)(fb1 + 2 * htid));
            const char* base = (const char*)(g_fw1T + 2 * htid);
            #pragma unroll
            for (int w = 0; w < 4; w++) {
                const int na = nacts[w];
                const u16* ap = act + w * 288;
                const u64* actq = (const u64*)ap;
                int a = 0;
                for (; a + 4 <= na; a += 4) {
                    u64 four = actq[a >> 2];
                    unsigned i0 = (unsigned)(four & 0xFFFFu);
                    unsigned i1 = (unsigned)((four >> 16) & 0xFFFFu);
                    unsigned i2 = (unsigned)((four >> 32) & 0xFFFFu);
                    unsigned i3 = (unsigned)(four >> 48);
                    u64 v0 = __ldg((const u64*)(base + i0 * (H1 * 4)));
                    u64 v1 = __ldg((const u64*)(base + i1 * (H1 * 4)));
                    u64 v2 = __ldg((const u64*)(base + i2 * (H1 * 4)));
                    u64 v3 = __ldg((const u64*)(base + i3 * (H1 * 4)));
                    acc = fadd2(acc, v0);
                    acc = fadd2(acc, v1);
                    acc = fadd2(acc, v2);
                    acc = fadd2(acc, v3);
                }
                for (; a < na; a++) {
                    unsigned i0 = ap[a];
                    acc = fadd2(acc, __ldg((const u64*)(base + i0 * (H1 * 4))));
                }
            }
            float lo, hi; unpack2(acc, lo, hi);
            float mn0 = lif_new_mem(m4a, lo);
            float mn1 = lif_new_mem(m4b, hi);
            m4a = mn0; m4b = mn1;
            *(u64*)(s4buf + 2 * htid) =
                pack2((mn0 > 1.0f) ? 1.0f : 0.0f, (mn1 > 1.0f) ? 1.0f : 0.0f);
        }
        barh(barid);   // S4

        // ======== fc2 (256->10) + output ========
        {
            #pragma unroll
            for (int i = 0; i < 3; i++) {
                int j = hwarp + 4 * i;
                if (j < NC) {
                    float acc = 0.0f;
                    #pragma unroll
                    for (int q = 0; q < 8; q++) {
                        int ii = lane + 32 * q;
                        acc = fmaf(__ldg(&fw2[j * H1 + ii]), s4buf[ii], acc);
                    }
                    #pragma unroll
                    for (int o = 16; o > 0; o >>= 1)
                        acc += __shfl_down_sync(0xffffffff, acc, o);
                    if (lane == 0) {
                        acc += __ldg(&fb2[j]);
                        float mn = lif_new_mem(m5r[i], acc);
                        m5r[i] = mn;
                        out[(t * BATCH + b) * NC + j] = (mn > 1.0f) ? 1.0f : 0.0f;
                    }
                }
            }
        }
        // no trailing barrier: fc2 reads only s4buf/fw2; s4's next writer (fc1)
        // is four barriers away; next conv1 writes s1p/xb whose readers are behind S1.
    }
}

extern "C" void kernel_launch(void* const* d_in, const int* in_sizes, int n_in,
                              void* d_out, int out_size) {
    const float* x   = (const float*)d_in[0];
    const float* w1  = (const float*)d_in[1];
    const float* b1  = (const float*)d_in[2];
    const float* w2  = (const float*)d_in[3];
    const float* b2  = (const float*)d_in[4];
    const float* w3  = (const float*)d_in[5];
    const float* b3  = (const float*)d_in[6];
    const float* fw1 = (const float*)d_in[7];
    const float* fb1 = (const float*)d_in[8];
    const float* fw2 = (const float*)d_in[9];
    const float* fb2 = (const float*)d_in[10];
    float* out = (float*)d_out;

    cudaFuncSetAttribute(snn_kernel, cudaFuncAttributeMaxDynamicSharedMemorySize, SMEM_BYTES);

    transpose_fw1_kernel<<<(H1 * F1 + 255) / 256, 256>>>(fw1);
    snn_kernel<<<BATCH / 2, NTHREADS, SMEM_BYTES>>>(x, w1, b1, w2, b2, w3, b3,
                                                    fb1, fw2, fb2, out);
}

// round 10
// speedup vs baseline: 1.0688x; 1.0688x over previous
#include <cuda_runtime.h>

#define BATCH   1024
#define TSTEPS  100
#define L0      30
#define C1      16
#define L1      24
#define K1      7
#define C2      32
#define L2      20
#define K2      5
#define C3      64
#define L3      18
#define K3      3
#define F1      1152   // 64*18
#define H1      256
#define NC      10

#define NTHREADS 256
#define S1ROW 52     // padded word stride per ci-pair, s1 (24 l * 2 + pad, mult of 4)
#define S2ROW 44     // padded word stride per ci-pair, s2 (20 l * 2 + pad, mult of 4)

typedef unsigned long long u64;
typedef unsigned short u16;

// Transposed fc1 weights: fw1T[i*H1 + j] = fw1[j*F1 + i]
__device__ __align__(16) float g_fw1T[F1 * H1];

__global__ void transpose_fw1_kernel(const float* __restrict__ fw1) {
    int idx = blockIdx.x * blockDim.x + threadIdx.x;
    if (idx < H1 * F1) {
        int j = idx / F1;
        int i = idx - j * F1;
        g_fw1T[i * H1 + j] = fw1[idx];
    }
}

// ---- f32x2 helpers ----
__device__ __forceinline__ u64 ffma2(u64 a, u64 b, u64 c) {
    u64 d; asm("fma.rn.f32x2 %0, %1, %2, %3;" : "=l"(d) : "l"(a), "l"(b), "l"(c)); return d;
}
__device__ __forceinline__ u64 fadd2(u64 a, u64 b) {
    u64 d; asm("add.rn.f32x2 %0, %1, %2;" : "=l"(d) : "l"(a), "l"(b)); return d;
}
__device__ __forceinline__ u64 pack2(float lo, float hi) {
    u64 r; asm("mov.b64 %0, {%1, %2};" : "=l"(r) : "f"(lo), "f"(hi)); return r;
}
__device__ __forceinline__ void unpack2(u64 v, float& lo, float& hi) {
    asm("mov.b64 {%0, %1}, %2;" : "=f"(lo), "=f"(hi) : "l"(v));
}
__device__ __forceinline__ u64 lds64(const float* p) { return *(const u64*)p; }

// half-scoped barrier: 128 threads, ids 1 (half 0) / 2 (half 1)
__device__ __forceinline__ void barh(int id) {
    asm volatile("bar.sync %0, 128;" :: "r"(id) : "memory");
}

// LIF: reset from PREVIOUS mem (subtract), spike on new mem.
// No FMA contraction: match reference op sequence 0.9*m + h - reset.
__device__ __forceinline__ float lif_new_mem(float m_old, float h) {
    float reset = (m_old > 1.0f) ? 1.0f : 0.0f;
    return __fadd_rn(__fadd_rn(__fmul_rn(0.9f, m_old), h), -reset);
}

// Dense conv on f32x2 ci-pairs; spike window read as even-aligned LDS.128
// pairs (2 l-positions per broadcast load). PARITY = l0 & 1; sbase must be
// pre-offset to the EVEN-aligned window start ((l0 - PARITY) * 2 words).
// Per output q the taps are applied d ascending, k ascending — identical
// accumulation order to R8 (bit-exact).
template<int LEN, int K, int NP, int COUT, int SROW, int PARITY>
__device__ __forceinline__ void conv_pair(const float* __restrict__ swp,
                                          const float* __restrict__ sbase,
                                          int co, u64 binit, u64* acc) {
    constexpr int NPAIR = (LEN + K + PARITY) / 2;   // covers rel d in [-PARITY, LEN+K-1)
    #pragma unroll
    for (int q = 0; q < LEN; q++) acc[q] = binit;
    #pragma unroll 4
    for (int p = 0; p < NP; p++) {
        u64 w[K];
        #pragma unroll
        for (int k = 0; k < K; k++)
            w[k] = lds64(swp + ((p * K + k) * COUT + co) * 2);
        const ulonglong2* sp = (const ulonglong2*)(sbase + p * SROW);
        #pragma unroll
        for (int dp = 0; dp < NPAIR; dp++) {
            ulonglong2 v = sp[dp];
            #pragma unroll
            for (int k = 0; k < K; k++) {
                int q0 = 2 * dp - PARITY - k;        // rel d of v.x minus k
                if (q0 >= 0 && q0 < LEN) acc[q0] = ffma2(w[k], v.x, acc[q0]);
            }
            #pragma unroll
            for (int k = 0; k < K; k++) {
                int q1 = 2 * dp + 1 - PARITY - k;    // rel d of v.y minus k
                if (q1 >= 0 && q1 < LEN) acc[q1] = ffma2(w[k], v.y, acc[q1]);
            }
        }
    }
}

// smem layout (words)
#define OFF_SW1T 0        // 112: [k*16+co]
#define OFF_SB1  112      // 16
#define OFF_SW2P 128      // 2560: [((p*5+k)*32+co)*2+e]
#define OFF_SW3P 2688     // 6144: [((p*3+k)*64+co)*2+e]
#define OFF_XB   8832     // 2*2*32 = 128: [half][buf][l]
#define OFF_S1   8960     // 2*416: [half][p*52 + l*2 + e]  (16B aligned)
#define OFF_S2   9792     // 2*704: [half][p*44 + l*2 + e]  (16B aligned)
#define OFF_S4   11200    // 2*256: [half][j]
#define OFF_MSK  11712    // 2*128: [half][T*64+co]
#define OFF_NACT 11968    // 2
#define OFF_ACT  11970    // 2*576 words = 2*1152 u16 (byte 47880, 8-aligned)
#define SMEM_WORDS 13122
#define SMEM_BYTES (SMEM_WORDS * 4)

__global__ __launch_bounds__(NTHREADS, 4)
void snn_kernel(const float* __restrict__ x,
                const float* __restrict__ w1, const float* __restrict__ b1,
                const float* __restrict__ w2, const float* __restrict__ b2,
                const float* __restrict__ w3, const float* __restrict__ b3,
                const float* __restrict__ fb1,
                const float* __restrict__ fw2, const float* __restrict__ fb2,
                float* __restrict__ out)
{
    extern __shared__ float smem[];
    float* sw1t = smem + OFF_SW1T;
    float* sb1  = smem + OFF_SB1;
    float* sw2p = smem + OFF_SW2P;
    float* sw3p = smem + OFF_SW3P;

    const int tid  = threadIdx.x;
    const int lane = tid & 31;
    const int warp = tid >> 5;
    const int half = warp >> 2;            // 0: warps 0-3 (sample A), 1: warps 4-7 (sample B)
    const int hwarp = warp & 3;
    const int htid = (hwarp << 5) | lane;  // 0..127 within half
    const int b = 2 * blockIdx.x + half;
    const int barid = 1 + half;

    float* xb    = smem + OFF_XB + half * 64;
    float* s1p   = smem + OFF_S1 + half * 416;   // [p*52 + l*2 + e]
    float* s2p   = smem + OFF_S2 + half * 704;   // [p*44 + l*2 + e]
    float* s4buf = smem + OFF_S4 + half * 256;
    unsigned* mkbuf = (unsigned*)(smem + OFF_MSK) + half * 128;
    int* nact = (int*)(smem + OFF_NACT) + half;
    u16* act = (u16*)(smem + OFF_ACT) + half * 1152;

    // ---- pack weights into smem (all 256 threads) ----
    for (int i = tid; i < C1 * K1; i += NTHREADS) {
        int co = i / K1, k = i - co * K1;
        sw1t[k * C1 + co] = w1[i];
    }
    if (tid < C1) sb1[tid] = b1[tid];
    for (int i = tid; i < C2 * C1 * K2; i += NTHREADS) {
        int co = i / (C1 * K2);
        int r = i - co * (C1 * K2);
        int ci = r / K2, k = r - ci * K2;
        sw2p[(((ci >> 1) * K2 + k) * C2 + co) * 2 + (ci & 1)] = w2[i];
    }
    for (int i = tid; i < C3 * C2 * K3; i += NTHREADS) {
        int co = i / (C2 * K3);
        int r = i - co * (C2 * K3);
        int ci = r / K3, k = r - ci * K3;
        sw3p[(((ci >> 1) * K3 + k) * C3 + co) * 2 + (ci & 1)] = w3[i];
    }
    // x prefetch for t=0
    if (hwarp == 0 && lane < L0)
        xb[lane] = __ldg(&x[b * (L0 * TSTEPS) + lane * TSTEPS]);

    // ---- per-thread register state ----
    float m1r[3] = {0.0f, 0.0f, 0.0f};
    const float b2r = b2[lane];
    float m2r[5] = {0.0f, 0.0f, 0.0f, 0.0f, 0.0f};
    const int l02 = hwarp * 5;                 // conv2: {5,5,5,5}, starts 0,5,10,15
    const int co3 = ((hwarp & 1) << 5) | lane; // conv3: {9,9}, starts 0,9
    const int T3  = hwarp >> 1;
    const int l03 = T3 * 9;
    const float b3r = b3[co3];
    float m3r[9];
    #pragma unroll
    for (int q = 0; q < 9; q++) m3r[q] = 0.0f;
    float m4a = 0.0f, m4b = 0.0f;
    float m5r[3] = {0.0f, 0.0f, 0.0f};
    __syncthreads();   // full-CTA: weights visible to both halves

    for (int t = 0; t < TSTEPS; t++) {
        // ======== conv1 (1->16, k=7): 128 threads/sample, 3 outputs each ========
        {
            const float* xr = xb + (t & 1) * 32;
            if (hwarp == 0 && lane < L0 && t + 1 < TSTEPS)
                xb[((t + 1) & 1) * 32 + lane] =
                    __ldg(&x[b * (L0 * TSTEPS) + lane * TSTEPS + t + 1]);
            #pragma unroll
            for (int it = 0; it < 3; it++) {
                int idx = htid + it * 128;
                int l = idx >> 4, co = idx & 15;
                float acc = sb1[co];
                #pragma unroll
                for (int k = 0; k < K1; k++)
                    acc = fmaf(sw1t[k * C1 + co], xr[l + k], acc);
                float mn = lif_new_mem(m1r[it], acc);
                m1r[it] = mn;
                s1p[(co >> 1) * S1ROW + l * 2 + (co & 1)] = (mn > 1.0f) ? 1.0f : 0.0f;
            }
        }
        barh(barid);   // S1

        // ======== conv2 (16->32, k=5): co=lane, 5 l per thread ========
        {
            u64 acc[5];
            const float* sb = s1p + (l02 & ~1) * 2;   // even-aligned window base
            if (hwarp & 1)
                conv_pair<5, K2, 8, C2, S1ROW, 1>(sw2p, sb, lane, pack2(b2r, 0.0f), acc);
            else
                conv_pair<5, K2, 8, C2, S1ROW, 0>(sw2p, sb, lane, pack2(b2r, 0.0f), acc);
            #pragma unroll
            for (int q = 0; q < 5; q++) {
                float lo, hi; unpack2(acc[q], lo, hi);
                float h = __fadd_rn(lo, hi);
                float mn = lif_new_mem(m2r[q], h);
                m2r[q] = mn;
                s2p[(lane >> 1) * S2ROW + (l02 + q) * 2 + (lane & 1)] = (mn > 1.0f) ? 1.0f : 0.0f;
            }
        }
        barh(barid);   // S2

        // ======== conv3 (32->64, k=3): co3, 9 l per thread ========
        {
            u64 acc[9];
            if (T3 == 0)
                conv_pair<9, K3, 16, C3, S2ROW, 0>(sw3p, s2p, co3, pack2(b3r, 0.0f), acc);
            else
                conv_pair<9, K3, 16, C3, S2ROW, 1>(sw3p, s2p + 8 * 2, co3, pack2(b3r, 0.0f), acc);
            unsigned bits = 0;
            #pragma unroll
            for (int q = 0; q < 9; q++) {
                float lo, hi; unpack2(acc[q], lo, hi);
                float h = __fadd_rn(lo, hi);
                float mn = lif_new_mem(m3r[q], h);
                m3r[q] = mn;
                if (mn > 1.0f) bits |= 1u << q;
            }
            mkbuf[T3 * 64 + co3] = bits;   // exclusive store, no atomics
        }
        barh(barid);   // S3

        // ======== build active-index list (one warp per half) ========
        if (hwarp == 1) {
            int r0 = 2 * lane, r1 = 2 * lane + 1;
            unsigned m0 = mkbuf[r0] | (mkbuf[64 + r0] << 9);   // 18 bits, l ascending
            unsigned m1 = mkbuf[r1] | (mkbuf[64 + r1] << 9);
            int cnt = __popc(m0) + __popc(m1);
            int pos = cnt;
            #pragma unroll
            for (int o = 1; o < 32; o <<= 1) {
                int v = __shfl_up_sync(0xffffffff, pos, o);
                if (lane >= o) pos += v;
            }
            if (lane == 31) *nact = pos;
            u16* ap = act + (pos - cnt);
            int base0 = r0 * L3;
            while (m0) {
                int l = __ffs(m0) - 1; m0 &= m0 - 1;
                *ap++ = (u16)(base0 + l);
            }
            int base1 = r1 * L3;
            while (m1) {
                int l = __ffs(m1) - 1; m1 &= m1 - 1;
                *ap++ = (u16)(base1 + l);
            }
        }
        barh(barid);   // S3b

        // ======== fc1 (1152->256): 128 threads/sample, 2 outputs each ========
        {
            const int na = *nact;
            u64 acc = __ldg((const u64*)(fb1 + 2 * htid));
            const char* base = (const char*)(g_fw1T + 2 * htid);
            const u64* actq = (const u64*)act;
            int a = 0;
            for (; a + 4 <= na; a += 4) {
                u64 four = actq[a >> 2];
                unsigned i0 = (unsigned)(four & 0xFFFFu);
                unsigned i1 = (unsigned)((four >> 16) & 0xFFFFu);
                unsigned i2 = (unsigned)((four >> 32) & 0xFFFFu);
                unsigned i3 = (unsigned)(four >> 48);
                u64 v0 = __ldg((const u64*)(base + i0 * (H1 * 4)));
                u64 v1 = __ldg((const u64*)(base + i1 * (H1 * 4)));
                u64 v2 = __ldg((const u64*)(base + i2 * (H1 * 4)));
                u64 v3 = __ldg((const u64*)(base + i3 * (H1 * 4)));
                acc = fadd2(acc, v0);
                acc = fadd2(acc, v1);
                acc = fadd2(acc, v2);
                acc = fadd2(acc, v3);
            }
            for (; a < na; a++) {
                unsigned i0 = act[a];
                acc = fadd2(acc, __ldg((const u64*)(base + i0 * (H1 * 4))));
            }
            float lo, hi; unpack2(acc, lo, hi);
            float mn0 = lif_new_mem(m4a, lo);
            float mn1 = lif_new_mem(m4b, hi);
            m4a = mn0; m4b = mn1;
            *(u64*)(s4buf + 2 * htid) =
                pack2((mn0 > 1.0f) ? 1.0f : 0.0f, (mn1 > 1.0f) ? 1.0f : 0.0f);
        }
        barh(barid);   // S4

        // ======== fc2 (256->10) + output ========
        {
            #pragma unroll
            for (int i = 0; i < 3; i++) {
                int j = hwarp + 4 * i;
                if (j < NC) {
                    float acc = 0.0f;
                    #pragma unroll
                    for (int q = 0; q < 8; q++) {
                        int ii = lane + 32 * q;
                        acc = fmaf(__ldg(&fw2[j * H1 + ii]), s4buf[ii], acc);
                    }
                    #pragma unroll
                    for (int o = 16; o > 0; o >>= 1)
                        acc += __shfl_down_sync(0xffffffff, acc, o);
                    if (lane == 0) {
                        acc += __ldg(&fb2[j]);
                        float mn = lif_new_mem(m5r[i], acc);
                        m5r[i] = mn;
                        out[(t * BATCH + b) * NC + j] = (mn > 1.0f) ? 1.0f : 0.0f;
                    }
                }
            }
        }
        // no trailing barrier: fc2 reads only s4buf/fw2; s4's next writer (fc1)
        // is four barriers away; next conv1 writes s1p/xb whose readers are behind S1.
    }
}

extern "C" void kernel_launch(void* const* d_in, const int* in_sizes, int n_in,
                              void* d_out, int out_size) {
    const float* x   = (const float*)d_in[0];
    const float* w1  = (const float*)d_in[1];
    const float* b1  = (const float*)d_in[2];
    const float* w2  = (const float*)d_in[3];
    const float* b2  = (const float*)d_in[4];
    const float* w3  = (const float*)d_in[5];
    const float* b3  = (const float*)d_in[6];
    const float* fw1 = (const float*)d_in[7];
    const float* fb1 = (const float*)d_in[8];
    const float* fw2 = (const float*)d_in[9];
    const float* fb2 = (const float*)d_in[10];
    float* out = (float*)d_out;

    cudaFuncSetAttribute(snn_kernel, cudaFuncAttributeMaxDynamicSharedMemorySize, SMEM_BYTES);

    transpose_fw1_kernel<<<(H1 * F1 + 255) / 256, 256>>>(fw1);
    snn_kernel<<<BATCH / 2, NTHREADS, SMEM_BYTES>>>(x, w1, b1, w2, b2, w3, b3,
                                                    fb1, fw2, fb2, out);
}

// round 11
// speedup vs baseline: 1.2565x; 1.1756x over previous
#include <cuda_runtime.h>

#define BATCH   1024
#define TSTEPS  100
#define L0      30
#define C1      16
#define L1      24
#define K1      7
#define C2      32
#define L2      20
#define K2      5
#define C3      64
#define L3      18
#define K3      3
#define F1      1152   // 64*18
#define H1      256
#define NC      10

#define NTHREADS 128
#define S1ROW 52     // padded word stride per ci-pair, s1
#define S2ROW 44     // padded word stride per ci-pair, s2

typedef unsigned long long u64;
typedef unsigned short u16;

// Transposed fc1 weights: fw1T[i*H1 + j] = fw1[j*F1 + i]
__device__ __align__(16) float g_fw1T[F1 * H1];
// Prepacked conv weights (interleaved ci-pairs), shared across CTAs via L1
__device__ __align__(16) float g_w2p[C1 * K2 * C2];   // [((ci/2)*K2+k)*C2+co]*2+e
__device__ __align__(16) float g_w3p[C2 * K3 * C3];   // [((ci/2)*K3+k)*C3+co]*2+e

__global__ void transpose_fw1_kernel(const float* __restrict__ fw1) {
    int idx = blockIdx.x * blockDim.x + threadIdx.x;
    if (idx < H1 * F1) {
        int j = idx / F1;
        int i = idx - j * F1;
        g_fw1T[i * H1 + j] = fw1[idx];
    }
}

__global__ void pack_weights_kernel(const float* __restrict__ w2,
                                    const float* __restrict__ w3) {
    int idx = blockIdx.x * blockDim.x + threadIdx.x;
    if (idx < C2 * C1 * K2) {
        int co = idx / (C1 * K2);
        int r = idx - co * (C1 * K2);
        int ci = r / K2, k = r - ci * K2;
        g_w2p[(((ci >> 1) * K2 + k) * C2 + co) * 2 + (ci & 1)] = w2[idx];
    }
    if (idx < C3 * C2 * K3) {
        int co = idx / (C2 * K3);
        int r = idx - co * (C2 * K3);
        int ci = r / K3, k = r - ci * K3;
        g_w3p[(((ci >> 1) * K3 + k) * C3 + co) * 2 + (ci & 1)] = w3[idx];
    }
}

// ---- f32x2 helpers ----
__device__ __forceinline__ u64 ffma2(u64 a, u64 b, u64 c) {
    u64 d; asm("fma.rn.f32x2 %0, %1, %2, %3;" : "=l"(d) : "l"(a), "l"(b), "l"(c)); return d;
}
__device__ __forceinline__ u64 fadd2(u64 a, u64 b) {
    u64 d; asm("add.rn.f32x2 %0, %1, %2;" : "=l"(d) : "l"(a), "l"(b)); return d;
}
__device__ __forceinline__ u64 pack2(float lo, float hi) {
    u64 r; asm("mov.b64 %0, {%1, %2};" : "=l"(r) : "f"(lo), "f"(hi)); return r;
}
__device__ __forceinline__ void unpack2(u64 v, float& lo, float& hi) {
    asm("mov.b64 {%0, %1}, %2;" : "=f"(lo), "=f"(hi) : "l"(v));
}
// L2-only load (keeps L1 for the hot weight set)
__device__ __forceinline__ u64 ldcg64(const void* p) {
    u64 d; asm volatile("ld.global.cg.b64 %0, [%1];" : "=l"(d) : "l"(p)); return d;
}

// LIF: reset from PREVIOUS mem (subtract), spike on new mem.
// No FMA contraction: match reference op sequence 0.9*m + h - reset.
__device__ __forceinline__ float lif_new_mem(float m_old, float h) {
    float reset = (m_old > 1.0f) ? 1.0f : 0.0f;
    return __fadd_rn(__fadd_rn(__fmul_rn(0.9f, m_old), h), -reset);
}

// Dense conv on f32x2 ci-pairs; spike window read as even-aligned LDS.128
// pairs; weights read via __ldg (warp-uniform -> 1-sector L1 hits, shared
// across all CTAs on the SM). Accumulation order identical to R10 (bit-exact).
template<int LEN, int K, int NP, int COUT, int SROW, int PARITY>
__device__ __forceinline__ void conv_pair(const float* __restrict__ gwp,
                                          const float* __restrict__ sbase,
                                          int co, u64 binit, u64* acc) {
    constexpr int NPAIR = (LEN + K + PARITY) / 2;
    #pragma unroll
    for (int q = 0; q < LEN; q++) acc[q] = binit;
    #pragma unroll 4
    for (int p = 0; p < NP; p++) {
        u64 w[K];
        #pragma unroll
        for (int k = 0; k < K; k++)
            w[k] = __ldg((const u64*)(gwp + ((p * K + k) * COUT + co) * 2));
        const ulonglong2* sp = (const ulonglong2*)(sbase + p * SROW);
        #pragma unroll
        for (int dp = 0; dp < NPAIR; dp++) {
            ulonglong2 v = sp[dp];
            #pragma unroll
            for (int k = 0; k < K; k++) {
                int q0 = 2 * dp - PARITY - k;
                if (q0 >= 0 && q0 < LEN) acc[q0] = ffma2(w[k], v.x, acc[q0]);
            }
            #pragma unroll
            for (int k = 0; k < K; k++) {
                int q1 = 2 * dp + 1 - PARITY - k;
                if (q1 >= 0 && q1 < LEN) acc[q1] = ffma2(w[k], v.y, acc[q1]);
            }
        }
    }
}

// smem layout (words), one sample per CTA
#define OFF_SW1T 0        // 112: [k*16+co]
#define OFF_SB1  112      // 16
#define OFF_XB   128      // 64: [buf*32 + l]
#define OFF_S1   192      // 416: [p*52 + l*2 + e]  (16B aligned)
#define OFF_S2   608      // 704: [p*44 + l*2 + e]  (16B aligned)
#define OFF_S4   1312     // 256: [j]
#define OFF_MSK  1568     // 128: [T*64+co]
#define OFF_NACT 1696     // 2 (1 + pad for 8B-aligned act)
#define OFF_ACT  1698     // 576 words = 1152 u16 (byte 6792, 8-aligned)
#define SMEM_WORDS 2274
#define SMEM_BYTES (SMEM_WORDS * 4)

__global__ __launch_bounds__(NTHREADS, 8)
void snn_kernel(const float* __restrict__ x,
                const float* __restrict__ w1, const float* __restrict__ b1,
                const float* __restrict__ b2v, const float* __restrict__ b3v,
                const float* __restrict__ fb1,
                const float* __restrict__ fw2, const float* __restrict__ fb2,
                float* __restrict__ out)
{
    extern __shared__ float smem[];
    float* sw1t = smem + OFF_SW1T;
    float* sb1  = smem + OFF_SB1;
    float* xb    = smem + OFF_XB;
    float* s1p   = smem + OFF_S1;
    float* s2p   = smem + OFF_S2;
    float* s4buf = smem + OFF_S4;
    unsigned* mkbuf = (unsigned*)(smem + OFF_MSK);
    int* nact = (int*)(smem + OFF_NACT);
    u16* act = (u16*)(smem + OFF_ACT);

    const int tid  = threadIdx.x;
    const int lane = tid & 31;
    const int warp = tid >> 5;            // 0..3
    const int b = blockIdx.x;             // one sample per CTA

    // ---- conv1 weights/biases into smem ----
    for (int i = tid; i < C1 * K1; i += NTHREADS) {
        int co = i / K1, k = i - co * K1;
        sw1t[k * C1 + co] = w1[i];
    }
    if (tid < C1) sb1[tid] = b1[tid];
    // x prefetch for t=0
    if (warp == 0 && lane < L0)
        xb[lane] = __ldg(&x[b * (L0 * TSTEPS) + lane * TSTEPS]);

    // ---- per-thread register state ----
    float m1r[3] = {0.0f, 0.0f, 0.0f};
    const float b2r = __ldg(&b2v[lane]);
    float m2r[5] = {0.0f, 0.0f, 0.0f, 0.0f, 0.0f};
    const int l02 = warp * 5;                  // conv2: {5,5,5,5}
    const int co3 = ((warp & 1) << 5) | lane;  // conv3: {9,9}
    const int T3  = warp >> 1;
    const float b3r = __ldg(&b3v[co3]);
    float m3r[9];
    #pragma unroll
    for (int q = 0; q < 9; q++) m3r[q] = 0.0f;
    float m4a = 0.0f, m4b = 0.0f;
    float m5r[3] = {0.0f, 0.0f, 0.0f};
    __syncthreads();

    for (int t = 0; t < TSTEPS; t++) {
        // ======== conv1 (1->16, k=7): 128 threads, 3 outputs each ========
        {
            const float* xr = xb + (t & 1) * 32;
            if (warp == 0 && lane < L0 && t + 1 < TSTEPS)
                xb[((t + 1) & 1) * 32 + lane] =
                    __ldg(&x[b * (L0 * TSTEPS) + lane * TSTEPS + t + 1]);
            #pragma unroll
            for (int it = 0; it < 3; it++) {
                int idx = tid + it * 128;
                int l = idx >> 4, co = idx & 15;
                float acc = sb1[co];
                #pragma unroll
                for (int k = 0; k < K1; k++)
                    acc = fmaf(sw1t[k * C1 + co], xr[l + k], acc);
                float mn = lif_new_mem(m1r[it], acc);
                m1r[it] = mn;
                s1p[(co >> 1) * S1ROW + l * 2 + (co & 1)] = (mn > 1.0f) ? 1.0f : 0.0f;
            }
        }
        __syncthreads();   // S1

        // ======== conv2 (16->32, k=5): co=lane, 5 l per thread ========
        {
            u64 acc[5];
            const float* sb = s1p + (l02 & ~1) * 2;
            if (warp & 1)
                conv_pair<5, K2, 8, C2, S1ROW, 1>(g_w2p, sb, lane, pack2(b2r, 0.0f), acc);
            else
                conv_pair<5, K2, 8, C2, S1ROW, 0>(g_w2p, sb, lane, pack2(b2r, 0.0f), acc);
            #pragma unroll
            for (int q = 0; q < 5; q++) {
                float lo, hi; unpack2(acc[q], lo, hi);
                float h = __fadd_rn(lo, hi);
                float mn = lif_new_mem(m2r[q], h);
                m2r[q] = mn;
                s2p[(lane >> 1) * S2ROW + (l02 + q) * 2 + (lane & 1)] = (mn > 1.0f) ? 1.0f : 0.0f;
            }
        }
        __syncthreads();   // S2

        // ======== conv3 (32->64, k=3): co3, 9 l per thread ========
        {
            u64 acc[9];
            if (T3 == 0)
                conv_pair<9, K3, 16, C3, S2ROW, 0>(g_w3p, s2p, co3, pack2(b3r, 0.0f), acc);
            else
                conv_pair<9, K3, 16, C3, S2ROW, 1>(g_w3p, s2p + 8 * 2, co3, pack2(b3r, 0.0f), acc);
            unsigned bits = 0;
            #pragma unroll
            for (int q = 0; q < 9; q++) {
                float lo, hi; unpack2(acc[q], lo, hi);
                float h = __fadd_rn(lo, hi);
                float mn = lif_new_mem(m3r[q], h);
                m3r[q] = mn;
                if (mn > 1.0f) bits |= 1u << q;
            }
            mkbuf[T3 * 64 + co3] = bits;   // exclusive store, no atomics
        }
        __syncthreads();   // S3

        // ======== build active-index list (warp 1) ========
        if (warp == 1) {
            int r0 = 2 * lane, r1 = 2 * lane + 1;
            unsigned m0 = mkbuf[r0] | (mkbuf[64 + r0] << 9);   // 18 bits, l ascending
            unsigned m1 = mkbuf[r1] | (mkbuf[64 + r1] << 9);
            int cnt = __popc(m0) + __popc(m1);
            int pos = cnt;
            #pragma unroll
            for (int o = 1; o < 32; o <<= 1) {
                int v = __shfl_up_sync(0xffffffff, pos, o);
                if (lane >= o) pos += v;
            }
            if (lane == 31) *nact = pos;
            u16* ap = act + (pos - cnt);
            int base0 = r0 * L3;
            while (m0) {
                int l = __ffs(m0) - 1; m0 &= m0 - 1;
                *ap++ = (u16)(base0 + l);
            }
            int base1 = r1 * L3;
            while (m1) {
                int l = __ffs(m1) - 1; m1 &= m1 - 1;
                *ap++ = (u16)(base1 + l);
            }
        }
        __syncthreads();   // S3b

        // ======== fc1 (1152->256): 128 threads, 2 outputs each ========
        {
            const int na = *nact;
            u64 acc = __ldg((const u64*)(fb1 + 2 * tid));
            const char* base = (const char*)(g_fw1T + 2 * tid);
            const u64* actq = (const u64*)act;
            int a = 0;
            for (; a + 4 <= na; a += 4) {
                u64 four = actq[a >> 2];
                unsigned i0 = (unsigned)(four & 0xFFFFu);
                unsigned i1 = (unsigned)((four >> 16) & 0xFFFFu);
                unsigned i2 = (unsigned)((four >> 32) & 0xFFFFu);
                unsigned i3 = (unsigned)(four >> 48);
                u64 v0 = ldcg64(base + i0 * (H1 * 4));
                u64 v1 = ldcg64(base + i1 * (H1 * 4));
                u64 v2 = ldcg64(base + i2 * (H1 * 4));
                u64 v3 = ldcg64(base + i3 * (H1 * 4));
                acc = fadd2(acc, v0);
                acc = fadd2(acc, v1);
                acc = fadd2(acc, v2);
                acc = fadd2(acc, v3);
            }
            for (; a < na; a++) {
                unsigned i0 = act[a];
                acc = fadd2(acc, ldcg64(base + i0 * (H1 * 4)));
            }
            float lo, hi; unpack2(acc, lo, hi);
            float mn0 = lif_new_mem(m4a, lo);
            float mn1 = lif_new_mem(m4b, hi);
            m4a = mn0; m4b = mn1;
            *(u64*)(s4buf + 2 * tid) =
                pack2((mn0 > 1.0f) ? 1.0f : 0.0f, (mn1 > 1.0f) ? 1.0f : 0.0f);
        }
        __syncthreads();   // S4

        // ======== fc2 (256->10) + output ========
        {
            #pragma unroll
            for (int i = 0; i < 3; i++) {
                int j = warp + 4 * i;
                if (j < NC) {
                    float acc = 0.0f;
                    #pragma unroll
                    for (int q = 0; q < 8; q++) {
                        int ii = lane + 32 * q;
                        acc = fmaf(__ldg(&fw2[j * H1 + ii]), s4buf[ii], acc);
                    }
                    #pragma unroll
                    for (int o = 16; o > 0; o >>= 1)
                        acc += __shfl_down_sync(0xffffffff, acc, o);
                    if (lane == 0) {
                        acc += __ldg(&fb2[j]);
                        float mn = lif_new_mem(m5r[i], acc);
                        m5r[i] = mn;
                        out[(t * BATCH + b) * NC + j] = (mn > 1.0f) ? 1.0f : 0.0f;
                    }
                }
            }
        }
        // no trailing barrier: fc2 reads only s4buf/fw2; s4's next writer (fc1)
        // is four barriers away; next conv1 writes s1p/xb whose readers are behind S1.
    }
}

extern "C" void kernel_launch(void* const* d_in, const int* in_sizes, int n_in,
                              void* d_out, int out_size) {
    const float* x   = (const float*)d_in[0];
    const float* w1  = (const float*)d_in[1];
    const float* b1  = (const float*)d_in[2];
    const float* w2  = (const float*)d_in[3];
    const float* b2  = (const float*)d_in[4];
    const float* w3  = (const float*)d_in[5];
    const float* b3  = (const float*)d_in[6];
    const float* fw1 = (const float*)d_in[7];
    const float* fb1 = (const float*)d_in[8];
    const float* fw2 = (const float*)d_in[9];
    const float* fb2 = (const float*)d_in[10];
    float* out = (float*)d_out;

    cudaFuncSetAttribute(snn_kernel, cudaFuncAttributeMaxDynamicSharedMemorySize, SMEM_BYTES);

    transpose_fw1_kernel<<<(H1 * F1 + 255) / 256, 256>>>(fw1);
    pack_weights_kernel<<<(C3 * C2 * K3 + 255) / 256, 256>>>(w2, w3);
    snn_kernel<<<BATCH, NTHREADS, SMEM_BYTES>>>(x, w1, b1, b2, b3,
                                                fb1, fw2, fb2, out);
}